// round 16
// baseline (speedup 1.0000x reference)
#include <cuda_runtime.h>
#include <cuda_fp16.h>
#include <cstdint>
#include <cstddef>

#define N    8192
#define FIN  512
#define FOUT 256
#define JT     64                 // j per chunk
#define SPLITS 4
#define JPART  (N / SPLITS)       // 2048
#define NCHUNK (JPART / JT)       // 32
#define ITILE  64                 // i rows per unit
#define NUNITS (128 * SPLITS)     // 512 work units
#define GRID_ATTN 296             // 2 CTAs x 148 SMs, persistent

// ---------------- scratch (no cudaMalloc allowed) ----------------
__device__ __half g_hT[FOUT * N];             // 4 MB  h^T fp16  [f][i]
__device__ __half g_Xhi[(size_t)N * FIN];     // 8 MB  X hi fp16 [i][k]
__device__ __half g_Xlo[(size_t)N * FIN];     // 8 MB  X lo fp16
__device__ __half g_WThi[FOUT * FIN];         // 256 KB W^T hi fp16 [f][k]
__device__ __half g_WTlo[FOUT * FIN];         // 256 KB W^T lo fp16
__device__ float  g_Wa1[FIN], g_Wa2[FIN];
__device__ float  g_t[N];                     // f2 * log2(e)
__device__ float  g_u[N];                     // f1 * log2(e)
__device__ int    g_maxbits;                  // max of (t + 64) as fp32 bits
__device__ int    g_unit;                     // persistent work queue counter
__device__ float  g_pnum[NUNITS * 64 * 256];  // partial numerators (33.5 MB)
__device__ float  g_pz[NUNITS * 64];          // partial Z

#define L2E 1.4426950408889634f

typedef unsigned long long ull;

// ---------------- PTX helpers (baseline sm_80+, legal at .target sm_100) ----
__device__ __forceinline__ uint32_t smem_u32(const void* p) {
    uint32_t a;
    asm("{ .reg .u64 t; cvta.to.shared.u64 t, %1; cvt.u32.u64 %0, t; }" : "=r"(a) : "l"(p));
    return a;
}
#define CP_ASYNC16(dst, src) \
    asm volatile("cp.async.cg.shared.global [%0], [%1], 16;" :: "r"((uint32_t)(dst)), "l"(src) : "memory")
#define CP_COMMIT() asm volatile("cp.async.commit_group;" ::: "memory")
#define CP_WAIT0()  asm volatile("cp.async.wait_group 0;" ::: "memory")

__device__ __forceinline__ void ldsm4(uint32_t* r, uint32_t addr) {
    asm volatile("ldmatrix.sync.aligned.m8n8.x4.shared.b16 {%0,%1,%2,%3}, [%4];"
        : "=r"(r[0]), "=r"(r[1]), "=r"(r[2]), "=r"(r[3]) : "r"(addr));
}
__device__ __forceinline__ void mmaf16(float* d, const uint32_t* a, uint32_t b0, uint32_t b1) {
    asm volatile("mma.sync.aligned.m16n8k16.row.col.f32.f16.f16.f32 "
        "{%0,%1,%2,%3}, {%4,%5,%6,%7}, {%8,%9}, {%0,%1,%2,%3};"
        : "+f"(d[0]), "+f"(d[1]), "+f"(d[2]), "+f"(d[3])
        : "r"(a[0]), "r"(a[1]), "r"(a[2]), "r"(a[3]), "r"(b0), "r"(b1));
}
__device__ __forceinline__ float ex2(float x) {
    float r; asm("ex2.approx.f32 %0, %1;" : "=f"(r) : "f"(x)); return r;
}
__device__ __forceinline__ uint32_t sw128(uint32_t off) { return off ^ ((off >> 3) & 0x70); }

// ---------------------------------------------------------------------------
// Kernel 1: Wa1 = W @ a1, Wa2 = W @ a2 (+ init global max, work counter)
// ---------------------------------------------------------------------------
__global__ void k_wa(const float* __restrict__ W,
                     const float* __restrict__ a1,
                     const float* __restrict__ a2) {
    __shared__ float a1s[FOUT], a2s[FOUT];
    int tid = threadIdx.x;
    if (blockIdx.x == 0 && tid == 0) { g_maxbits = 0; g_unit = 0; }
    if (tid < FOUT) { a1s[tid] = a1[tid]; a2s[tid] = a2[tid]; }
    __syncthreads();
    int warp = tid >> 5, lane = tid & 31;
    int row = blockIdx.x * 8 + warp;
    const float* wr = W + (size_t)row * FOUT;
    float s1 = 0.f, s2 = 0.f;
    for (int c = lane; c < FOUT; c += 32) {
        float w = wr[c];
        s1 += w * a1s[c];
        s2 += w * a2s[c];
    }
    #pragma unroll
    for (int o = 16; o; o >>= 1) {
        s1 += __shfl_down_sync(0xFFFFFFFFu, s1, o);
        s2 += __shfl_down_sync(0xFFFFFFFFu, s2, o);
    }
    if (lane == 0) { g_Wa1[row] = s1; g_Wa2[row] = s2; }
}

// ---------------------------------------------------------------------------
// Kernel 2: exact fp32 logits f1,f2 -> log2-domain t,u + global max(t)
// ---------------------------------------------------------------------------
__global__ void k_f(const float* __restrict__ X) {
    __shared__ float wa1[FIN], wa2[FIN];
    int tid = threadIdx.x;
    for (int c = tid; c < FIN; c += 256) { wa1[c] = g_Wa1[c]; wa2[c] = g_Wa2[c]; }
    __syncthreads();
    int warp = tid >> 5, lane = tid & 31;
    int row = blockIdx.x * 8 + warp;
    const float* xr = X + (size_t)row * FIN;
    float s1 = 0.f, s2 = 0.f;
    for (int c = lane; c < FIN; c += 32) {
        float x = xr[c];
        s1 += x * wa1[c];
        s2 += x * wa2[c];
    }
    #pragma unroll
    for (int o = 16; o; o >>= 1) {
        s1 += __shfl_down_sync(0xFFFFFFFFu, s1, o);
        s2 += __shfl_down_sync(0xFFFFFFFFu, s2, o);
    }
    if (lane == 0) {
        float t = s2 * L2E;
        g_t[row] = t;
        g_u[row] = s1 * L2E;
        atomicMax(&g_maxbits, __float_as_int(t + 64.f));   // t+64 > 0 always
    }
}

// ---------------------------------------------------------------------------
// Kernel 2b: X -> fp16 hi/lo, [i][k] layout (B operand for k_gemm2)
// ---------------------------------------------------------------------------
__global__ __launch_bounds__(256) void k_xc(const float* __restrict__ X) {
    int gid = blockIdx.x * 256 + threadIdx.x;
    float4 x = ((const float4*)X)[gid];
    __half h0 = __float2half(x.x), h1 = __float2half(x.y);
    __half h2 = __float2half(x.z), h3 = __float2half(x.w);
    __half2 hhi0 = __halves2half2(h0, h1), hhi1 = __halves2half2(h2, h3);
    __half2 hlo0 = __floats2half2_rn(x.x - __half2float(h0), x.y - __half2float(h1));
    __half2 hlo1 = __floats2half2_rn(x.z - __half2float(h2), x.w - __half2float(h3));
    uint2 vhi = make_uint2(*(uint32_t*)&hhi0, *(uint32_t*)&hhi1);
    uint2 vlo = make_uint2(*(uint32_t*)&hlo0, *(uint32_t*)&hlo1);
    ((uint2*)g_Xhi)[gid] = vhi;
    ((uint2*)g_Xlo)[gid] = vlo;
}

// ---------------------------------------------------------------------------
// Kernel 2c: W -> W^T fp16 hi/lo via smem tile (coalesced both sides)
// grid (FIN/32, FOUT/32), block (32, 8)
// ---------------------------------------------------------------------------
__global__ __launch_bounds__(256) void k_wt(const float* __restrict__ W) {
    __shared__ float tile[32][33];
    int k0 = blockIdx.x * 32, f0 = blockIdx.y * 32;
    int tx = threadIdx.x, ty = threadIdx.y;
    #pragma unroll
    for (int q = 0; q < 4; q++) {
        int kr = ty + q * 8;
        tile[kr][tx] = W[(size_t)(k0 + kr) * FOUT + f0 + tx];
    }
    __syncthreads();
    #pragma unroll
    for (int q = 0; q < 4; q++) {
        int fr = ty + q * 8;
        float w = tile[tx][fr];
        __half hi = __float2half(w);
        __half lo = __float2half(w - __half2float(hi));
        g_WThi[(size_t)(f0 + fr) * FIN + k0 + tx] = hi;
        g_WTlo[(size_t)(f0 + fr) * FIN + k0 + tx] = lo;
    }
}

// ---------------------------------------------------------------------------
// Kernel 3: h^T = W^T @ X^T via fp16 mma.sync, 3 chains (exact to ~2^-22).
// grid (FOUT/64, N/256) = (4, 32), 256 threads, single 80KB stage, occ 2.
// ---------------------------------------------------------------------------
#define G_AHI 0
#define G_ALO 8192
#define G_BHI 16384
#define G_BLO 49152
#define SMEM_GEMM 81920

__global__ __launch_bounds__(256, 2) void k_gemm2() {
    extern __shared__ char smem[];
    const uint32_t sb = smem_u32(smem);
    const int tid = threadIdx.x;
    const int f0 = blockIdx.x * 64;
    const int i0 = blockIdx.y * 256;

    const int warp = tid >> 5, lane = tid & 31;
    const int mw = warp >> 2;
    const int fw = warp & 3;
    const int gr = lane >> 3, lr = lane & 7;
    const int a_rbase = mw * 32 + lr + (gr & 1) * 8;
    const int a_koff = (gr >> 1) * 8;
    const int b_roff = fw * 64 + lr + (gr >> 1) * 8;
    const int b_koff = (gr & 1) * 8;

    float acc[64];
    #pragma unroll
    for (int q = 0; q < 64; q++) acc[q] = 0.f;

    for (int kc = 0; kc < FIN; kc += 64) {
        #pragma unroll
        for (int v = 0; v < 2; v++) {
            int idx = tid * 2 + v;
            int row = idx >> 3, seg = idx & 7;
            uint32_t sw = sw128((uint32_t)(row * 128 + seg * 16));
            const size_t off = (size_t)(f0 + row) * FIN + kc + seg * 8;
            CP_ASYNC16(sb + G_AHI + sw, g_WThi + off);
            CP_ASYNC16(sb + G_ALO + sw, g_WTlo + off);
        }
        {
            const size_t off = (size_t)(i0 + tid) * FIN + kc;
            #pragma unroll
            for (int q = 0; q < 8; q++) {
                uint32_t sw = sw128((uint32_t)(tid * 128 + q * 16));
                CP_ASYNC16(sb + G_BHI + sw, g_Xhi + off + q * 8);
                CP_ASYNC16(sb + G_BLO + sw, g_Xlo + off + q * 8);
            }
        }
        CP_COMMIT();
        CP_WAIT0();
        __syncthreads();
        #pragma unroll
        for (int k0 = 0; k0 < 64; k0 += 16) {
            uint32_t Ahi0[4], Alo0[4], Ahi1[4], Alo1[4];
            uint32_t ao0 = sw128((uint32_t)(a_rbase * 128 + (k0 + a_koff) * 2));
            uint32_t ao1 = sw128((uint32_t)((a_rbase + 16) * 128 + (k0 + a_koff) * 2));
            ldsm4(Ahi0, sb + G_AHI + ao0);
            ldsm4(Alo0, sb + G_ALO + ao0);
            ldsm4(Ahi1, sb + G_AHI + ao1);
            ldsm4(Alo1, sb + G_ALO + ao1);
            #pragma unroll
            for (int nb = 0; nb < 4; nb++) {
                uint32_t boff = sw128((uint32_t)((b_roff + nb * 16) * 128 + (k0 + b_koff) * 2));
                uint32_t Bh[4], Bl[4];
                ldsm4(Bh, sb + G_BHI + boff);
                ldsm4(Bl, sb + G_BLO + boff);
                float* d00 = acc + nb * 8;
                float* d01 = acc + nb * 8 + 4;
                float* d10 = acc + 32 + nb * 8;
                float* d11 = acc + 32 + nb * 8 + 4;
                mmaf16(d00, Ahi0, Bh[0], Bh[1]);
                mmaf16(d01, Ahi0, Bh[2], Bh[3]);
                mmaf16(d10, Ahi1, Bh[0], Bh[1]);
                mmaf16(d11, Ahi1, Bh[2], Bh[3]);
                mmaf16(d00, Ahi0, Bl[0], Bl[1]);
                mmaf16(d01, Ahi0, Bl[2], Bl[3]);
                mmaf16(d10, Ahi1, Bl[0], Bl[1]);
                mmaf16(d11, Ahi1, Bl[2], Bl[3]);
                mmaf16(d00, Alo0, Bh[0], Bh[1]);
                mmaf16(d01, Alo0, Bh[2], Bh[3]);
                mmaf16(d10, Alo1, Bh[0], Bh[1]);
                mmaf16(d11, Alo1, Bh[2], Bh[3]);
            }
        }
        __syncthreads();
    }

    {
        const int qr = lane >> 2, qc = lane & 3;
        #pragma unroll
        for (int mt = 0; mt < 2; mt++) {
            int fr = f0 + mw * 32 + mt * 16 + qr;
            #pragma unroll
            for (int nb = 0; nb < 4; nb++) {
                const float* a = acc + mt * 32 + nb * 8;
                int col = i0 + fw * 64 + nb * 16 + 2 * qc;
                __half2 v0 = __floats2half2_rn(a[0], a[1]);
                __half2 v1 = __floats2half2_rn(a[2], a[3]);
                __half2 v2 = __floats2half2_rn(a[4], a[5]);
                __half2 v3 = __floats2half2_rn(a[6], a[7]);
                *(__half2*)(g_hT + (size_t)fr * N + col)           = v0;
                *(__half2*)(g_hT + (size_t)(fr + 8) * N + col)     = v1;
                *(__half2*)(g_hT + (size_t)fr * N + col + 8)       = v2;
                *(__half2*)(g_hT + (size_t)(fr + 8) * N + col + 8) = v3;
            }
        }
    }
}

// ---------------------------------------------------------------------------
// Kernel 4: PERSISTENT masked-softmax aggregation (fp16 mma.sync, 1 chain).
// grid = 296 CTAs (2/SM), atomic work queue of 512 (i_tile, split) units,
// each 64 i x 2048 j (32 chunks). Inner loop identical to R13/R14 best.
// Output per unit (pnum/pz slot) is assignment-independent -> deterministic.
// ---------------------------------------------------------------------------
#define STAGE 40960
#define OFF_A(s) ((s) * STAGE)
#define OFF_B(s) ((s) * STAGE + 8192)
#define SMEM_ATTN (2 * STAGE)   // 81920

__global__ __launch_bounds__(256, 2) void k_attn(const int* __restrict__ adj) {
    extern __shared__ char smem[];
    __shared__ int s_unit;
    const uint32_t sb = smem_u32(smem);
    const int tid = threadIdx.x;

    const int warp = tid >> 5, lane = tid & 31;
    const int mw = warp >> 2;
    const int fw = warp & 3;
    const int gr = lane >> 3, lr = lane & 7;
    const int a_rbase = mw * 32 + lr + (gr & 1) * 8;
    const int a_koff = (gr >> 1) * 8;
    const int b_roff = fw * 64 + lr + (gr >> 1) * 8;
    const int b_koff = (gr & 1) * 8;
    const int il = tid >> 2;
    const int jb = (tid & 3) * 16;
    const float Tmax = __int_as_float(g_maxbits) - 64.f;   // max_j t_j

    while (true) {
        if (tid == 0) s_unit = atomicAdd(&g_unit, 1);
        __syncthreads();
        const int u = s_unit;
        if (u >= NUNITS) break;
        const int i0 = (u & 127) * ITILE;
        const int jbase = (u >> 7) * JPART;

        const float uu = g_u[i0 + il];
        float kk;
        {
            float smax = uu + Tmax;
            float b = (smax >= 0.f) ? smax : 0.2f * smax;
            kk = 13.f - floorf(b);
        }
        const int* adjrow = adj + (size_t)(i0 + il) * N;
        float zacc = 0.f;

        float acc[64];
        #pragma unroll
        for (int q = 0; q < 64; q++) acc[q] = 0.f;

        auto fillB = [&](int s, int jglob) {
            const __half* src = g_hT + (size_t)tid * N + jglob;
            #pragma unroll
            for (int q = 0; q < 8; q++) {
                uint32_t sw = sw128(tid * 128 + q * 16);
                CP_ASYNC16(sb + OFF_B(s) + sw, src + q * 8);
            }
        };
        auto genA = [&](int s, const int4* am4, int jglob) {
            const int* am = (const int*)am4;
            const float4* tp = (const float4*)(g_t + jglob + jb);
            float tv[16];
            #pragma unroll
            for (int q = 0; q < 4; q++) {
                float4 t4 = tp[q];
                tv[q * 4 + 0] = t4.x;
                tv[q * 4 + 1] = t4.y;
                tv[q * 4 + 2] = t4.z;
                tv[q * 4 + 3] = t4.w;
            }
            uint32_t phv[8];
            #pragma unroll
            for (int p = 0; p < 8; p++) {
                float w[2];
                #pragma unroll
                for (int e = 0; e < 2; e++) {
                    int jj = p * 2 + e;
                    float s_ = tv[jj] + uu;
                    float ee = (s_ >= 0.f) ? s_ : 0.2f * s_;
                    float wv = ex2(ee + kk);
                    w[e] = am[jj] ? wv : 0.f;
                }
                __half2 hh = __floats2half2_rn(w[0], w[1]);
                zacc += __low2float(hh) + __high2float(hh);
                phv[p] = *(uint32_t*)&hh;
            }
            uint32_t sw0 = sw128((uint32_t)(il * 128 + jb * 2));
            uint32_t sw1 = sw128((uint32_t)(il * 128 + jb * 2 + 16));
            *(uint4*)(smem + OFF_A(s) + sw0) = make_uint4(phv[0], phv[1], phv[2], phv[3]);
            *(uint4*)(smem + OFF_A(s) + sw1) = make_uint4(phv[4], phv[5], phv[6], phv[7]);
        };

        {
            int4 aR[4];
            const int4* ap = (const int4*)(adjrow + jbase + jb);
            aR[0] = ap[0]; aR[1] = ap[1]; aR[2] = ap[2]; aR[3] = ap[3];
            fillB(0, jbase);
            CP_COMMIT();
            genA(0, aR, jbase);
            CP_WAIT0();
            __syncthreads();
        }

        for (int c = 0; c < NCHUNK; c++) {
            const int s = c & 1;
            const bool more = (c + 1 < NCHUNK);
            int4 aR[4];
            int jn = jbase + (c + 1) * JT;
            if (more) {
                const int4* ap = (const int4*)(adjrow + jn + jb);
                aR[0] = ap[0]; aR[1] = ap[1]; aR[2] = ap[2]; aR[3] = ap[3];
                fillB(s ^ 1, jn);
                CP_COMMIT();
            }
            #pragma unroll
            for (int k0 = 0; k0 < JT; k0 += 16) {
                uint32_t A0[4], A1[4], B[4][4];
                uint32_t ao0 = sw128((uint32_t)(a_rbase * 128 + (k0 + a_koff) * 2));
                uint32_t ao1 = sw128((uint32_t)((a_rbase + 16) * 128 + (k0 + a_koff) * 2));
                ldsm4(A0, sb + OFF_A(s) + ao0);
                ldsm4(A1, sb + OFF_A(s) + ao1);
                #pragma unroll
                for (int nb = 0; nb < 4; nb++) {
                    uint32_t boff = sw128((uint32_t)((b_roff + nb * 16) * 128 + (k0 + b_koff) * 2));
                    ldsm4(B[nb], sb + OFF_B(s) + boff);
                }
                #pragma unroll
                for (int nb = 0; nb < 4; nb++) {
                    mmaf16(acc + nb * 8,          A0, B[nb][0], B[nb][1]);
                    mmaf16(acc + nb * 8 + 4,      A0, B[nb][2], B[nb][3]);
                    mmaf16(acc + 32 + nb * 8,     A1, B[nb][0], B[nb][1]);
                    mmaf16(acc + 32 + nb * 8 + 4, A1, B[nb][2], B[nb][3]);
                }
            }
            if (more) {
                genA(s ^ 1, aR, jn);
                CP_WAIT0();
            }
            __syncthreads();
        }

        // ---- Z partial ----
        float zred = zacc + __shfl_xor_sync(0xFFFFFFFFu, zacc, 1);
        zred += __shfl_xor_sync(0xFFFFFFFFu, zred, 2);
        if ((tid & 3) == 0) g_pz[u * ITILE + il] = zred;

        // ---- accumulators -> gmem partial numerators ----
        {
            const int qr = lane >> 2, qc = lane & 3;
            #pragma unroll
            for (int mt = 0; mt < 2; mt++) {
                int r0 = mw * 32 + mt * 16 + qr;
                float* base0 = g_pnum + (size_t)u * (ITILE * 256)
                             + (size_t)r0 * 256 + fw * 64 + 2 * qc;
                float* base1 = base0 + 8 * 256;
                #pragma unroll
                for (int nb = 0; nb < 4; nb++) {
                    const float* a = acc + mt * 32 + nb * 8;
                    *(float2*)(base0 + nb * 16)     = make_float2(a[0], a[1]);
                    *(float2*)(base1 + nb * 16)     = make_float2(a[2], a[3]);
                    *(float2*)(base0 + nb * 16 + 8) = make_float2(a[4], a[5]);
                    *(float2*)(base1 + nb * 16 + 8) = make_float2(a[6], a[7]);
                }
            }
        }
        __syncthreads();   // all threads done with this unit before next grab
    }
}

// ---------------------------------------------------------------------------
// Kernel 5: combine 4 splits, normalize, ELU
// ---------------------------------------------------------------------------
__global__ __launch_bounds__(256) void k_comb(float* __restrict__ out) {
    int gid = blockIdx.x * 256 + threadIdx.x;   // float4 index
    int i = gid >> 6;
    int c4 = (gid & 63) * 4;
    int it = i >> 6, row = i & 63;
    float4 n = make_float4(0.f, 0.f, 0.f, 0.f);
    float z = 0.f;
    #pragma unroll
    for (int sp = 0; sp < SPLITS; sp++) {
        int u = sp * 128 + it;
        const float4 p = *(const float4*)(g_pnum + (size_t)u * (ITILE * 256)
                                          + (size_t)row * 256 + c4);
        n.x += p.x; n.y += p.y; n.z += p.z; n.w += p.w;
        z += g_pz[u * ITILE + row];
    }
    float inv = 1.f / z;
    float v0 = n.x * inv, v1 = n.y * inv, v2 = n.z * inv, v3 = n.w * inv;
    float4 o;
    o.x = (v0 > 0.f) ? v0 : expm1f(v0);
    o.y = (v1 > 0.f) ? v1 : expm1f(v1);
    o.z = (v2 > 0.f) ? v2 : expm1f(v2);
    o.w = (v3 > 0.f) ? v3 : expm1f(v3);
    *(float4*)(out + (size_t)i * FOUT + c4) = o;
}

// ---------------------------------------------------------------------------
extern "C" void kernel_launch(void* const* d_in, const int* in_sizes, int n_in,
                              void* d_out, int out_size) {
    (void)in_sizes; (void)n_in; (void)out_size;
    const float* X   = (const float*)d_in[0];
    const int*   adj = (const int*)d_in[1];
    const float* W   = (const float*)d_in[2];
    const float* a1  = (const float*)d_in[3];
    const float* a2  = (const float*)d_in[4];
    float* out = (float*)d_out;

    cudaFuncSetAttribute(k_attn, cudaFuncAttributeMaxDynamicSharedMemorySize, SMEM_ATTN);
    cudaFuncSetAttribute(k_gemm2, cudaFuncAttributeMaxDynamicSharedMemorySize, SMEM_GEMM);

    k_wa<<<FIN / 8, 256>>>(W, a1, a2);
    k_f<<<N / 8, 256>>>(X);
    k_xc<<<(N * FIN / 4) / 256, 256>>>(X);
    k_wt<<<dim3(FIN / 32, FOUT / 32), dim3(32, 8)>>>(W);
    k_gemm2<<<dim3(FOUT / 64, N / 256), 256, SMEM_GEMM>>>();
    k_attn<<<GRID_ATTN, 256, SMEM_ATTN>>>(adj);
    k_comb<<<(N * FOUT / 4) / 256, 256>>>(out);
}

// round 17
// speedup vs baseline: 1.0180x; 1.0180x over previous
#include <cuda_runtime.h>
#include <cuda_fp16.h>
#include <cstdint>
#include <cstddef>

#define N    8192
#define FIN  512
#define FOUT 256
#define JT     64                 // j per chunk
#define SPLITS 2
#define JHALF  (N / SPLITS)       // 4096
#define NCHUNK (JHALF / JT)       // 64
#define ITILE  64                 // i rows per CTA

// ---------------- scratch (no cudaMalloc allowed) ----------------
__device__ __half g_hT[FOUT * N];             // 4 MB  h^T fp16  [f][i]
__device__ __half g_Xhi[(size_t)N * FIN];     // 8 MB  X hi fp16 [i][k]
__device__ __half g_Xlo[(size_t)N * FIN];     // 8 MB  X lo fp16
__device__ __half g_WThi[FOUT * FIN];         // 256 KB W^T hi fp16 [f][k]
__device__ __half g_WTlo[FOUT * FIN];         // 256 KB W^T lo fp16
__device__ float  g_Wa1[FIN], g_Wa2[FIN];
__device__ float  g_t[N];                     // f2 * log2(e)
__device__ float  g_u[N];                     // f1 * log2(e)
__device__ int    g_maxbits;                  // max of (t + 64) as fp32 bits
__device__ float  g_pnum[256 * 64 * 256];     // partial numerators (16.8 MB)
__device__ float  g_pz[256 * 64];             // partial Z

#define L2E 1.4426950408889634f

typedef unsigned long long ull;

// ---------------- PTX helpers (baseline sm_80+, legal at .target sm_100) ----
__device__ __forceinline__ uint32_t smem_u32(const void* p) {
    uint32_t a;
    asm("{ .reg .u64 t; cvta.to.shared.u64 t, %1; cvt.u32.u64 %0, t; }" : "=r"(a) : "l"(p));
    return a;
}
#define CP_ASYNC16(dst, src) \
    asm volatile("cp.async.cg.shared.global [%0], [%1], 16;" :: "r"((uint32_t)(dst)), "l"(src) : "memory")
#define CP_COMMIT() asm volatile("cp.async.commit_group;" ::: "memory")
#define CP_WAIT0()  asm volatile("cp.async.wait_group 0;" ::: "memory")

__device__ __forceinline__ void ldsm4(uint32_t* r, uint32_t addr) {
    asm volatile("ldmatrix.sync.aligned.m8n8.x4.shared.b16 {%0,%1,%2,%3}, [%4];"
        : "=r"(r[0]), "=r"(r[1]), "=r"(r[2]), "=r"(r[3]) : "r"(addr));
}
__device__ __forceinline__ void mmaf16(float* d, const uint32_t* a, uint32_t b0, uint32_t b1) {
    asm volatile("mma.sync.aligned.m16n8k16.row.col.f32.f16.f16.f32 "
        "{%0,%1,%2,%3}, {%4,%5,%6,%7}, {%8,%9}, {%0,%1,%2,%3};"
        : "+f"(d[0]), "+f"(d[1]), "+f"(d[2]), "+f"(d[3])
        : "r"(a[0]), "r"(a[1]), "r"(a[2]), "r"(a[3]), "r"(b0), "r"(b1));
}
__device__ __forceinline__ float ex2(float x) {
    float r; asm("ex2.approx.f32 %0, %1;" : "=f"(r) : "f"(x)); return r;
}
__device__ __forceinline__ uint32_t sw128(uint32_t off) { return off ^ ((off >> 3) & 0x70); }

// ---------------------------------------------------------------------------
// Kernel 1: Wa1 = W @ a1, Wa2 = W @ a2 (+ init global max)
// ---------------------------------------------------------------------------
__global__ void k_wa(const float* __restrict__ W,
                     const float* __restrict__ a1,
                     const float* __restrict__ a2) {
    __shared__ float a1s[FOUT], a2s[FOUT];
    int tid = threadIdx.x;
    if (blockIdx.x == 0 && tid == 0) g_maxbits = 0;
    if (tid < FOUT) { a1s[tid] = a1[tid]; a2s[tid] = a2[tid]; }
    __syncthreads();
    int warp = tid >> 5, lane = tid & 31;
    int row = blockIdx.x * 8 + warp;
    const float* wr = W + (size_t)row * FOUT;
    float s1 = 0.f, s2 = 0.f;
    for (int c = lane; c < FOUT; c += 32) {
        float w = wr[c];
        s1 += w * a1s[c];
        s2 += w * a2s[c];
    }
    #pragma unroll
    for (int o = 16; o; o >>= 1) {
        s1 += __shfl_down_sync(0xFFFFFFFFu, s1, o);
        s2 += __shfl_down_sync(0xFFFFFFFFu, s2, o);
    }
    if (lane == 0) { g_Wa1[row] = s1; g_Wa2[row] = s2; }
}

// ---------------------------------------------------------------------------
// Kernel 2: one pass over X: exact fp32 logits -> t,u + global max(t),
// AND X -> fp16 hi/lo conversion (saves a second 16 MB read of X).
// grid N/8 = 1024 blocks, 256 threads; warp w owns row blockIdx*8+w.
// ---------------------------------------------------------------------------
__global__ void k_f(const float* __restrict__ X) {
    __shared__ float wa1[FIN], wa2[FIN];
    int tid = threadIdx.x;
    for (int c = tid; c < FIN; c += 256) { wa1[c] = g_Wa1[c]; wa2[c] = g_Wa2[c]; }
    __syncthreads();
    int warp = tid >> 5, lane = tid & 31;
    int row = blockIdx.x * 8 + warp;
    const float* xr = X + (size_t)row * FIN;
    __half* xh = g_Xhi + (size_t)row * FIN;
    __half* xl = g_Xlo + (size_t)row * FIN;
    float s1 = 0.f, s2 = 0.f;
    #pragma unroll 4
    for (int c = lane; c < FIN; c += 32) {
        float x = xr[c];
        s1 += x * wa1[c];
        s2 += x * wa2[c];
        __half hi = __float2half(x);
        xh[c] = hi;
        xl[c] = __float2half(x - __half2float(hi));
    }
    #pragma unroll
    for (int o = 16; o; o >>= 1) {
        s1 += __shfl_down_sync(0xFFFFFFFFu, s1, o);
        s2 += __shfl_down_sync(0xFFFFFFFFu, s2, o);
    }
    if (lane == 0) {
        float t = s2 * L2E;
        g_t[row] = t;
        g_u[row] = s1 * L2E;
        atomicMax(&g_maxbits, __float_as_int(t + 64.f));   // t+64 > 0 always
    }
}

// ---------------------------------------------------------------------------
// Kernel 2c: W -> W^T fp16 hi/lo via smem tile (coalesced both sides)
// ---------------------------------------------------------------------------
__global__ __launch_bounds__(256) void k_wt(const float* __restrict__ W) {
    __shared__ float tile[32][33];
    int k0 = blockIdx.x * 32, f0 = blockIdx.y * 32;
    int tx = threadIdx.x, ty = threadIdx.y;
    #pragma unroll
    for (int q = 0; q < 4; q++) {
        int kr = ty + q * 8;
        tile[kr][tx] = W[(size_t)(k0 + kr) * FOUT + f0 + tx];
    }
    __syncthreads();
    #pragma unroll
    for (int q = 0; q < 4; q++) {
        int fr = ty + q * 8;
        float w = tile[tx][fr];
        __half hi = __float2half(w);
        __half lo = __float2half(w - __half2float(hi));
        g_WThi[(size_t)(f0 + fr) * FIN + k0 + tx] = hi;
        g_WTlo[(size_t)(f0 + fr) * FIN + k0 + tx] = lo;
    }
}

// ---------------------------------------------------------------------------
// Kernel 3: h^T = W^T @ X^T via fp16 mma.sync, 3 chains (exact to ~2^-22).
// grid (FOUT/64, N/256) = (4, 32), 256 threads, single 80KB stage, occ 2.
// ---------------------------------------------------------------------------
#define G_AHI 0
#define G_ALO 8192
#define G_BHI 16384
#define G_BLO 49152
#define SMEM_GEMM 81920

__global__ __launch_bounds__(256, 2) void k_gemm2() {
    extern __shared__ char smem[];
    const uint32_t sb = smem_u32(smem);
    const int tid = threadIdx.x;
    const int f0 = blockIdx.x * 64;
    const int i0 = blockIdx.y * 256;

    const int warp = tid >> 5, lane = tid & 31;
    const int mw = warp >> 2;
    const int fw = warp & 3;
    const int gr = lane >> 3, lr = lane & 7;
    const int a_rbase = mw * 32 + lr + (gr & 1) * 8;
    const int a_koff = (gr >> 1) * 8;
    const int b_roff = fw * 64 + lr + (gr >> 1) * 8;
    const int b_koff = (gr & 1) * 8;

    float acc[64];
    #pragma unroll
    for (int q = 0; q < 64; q++) acc[q] = 0.f;

    for (int kc = 0; kc < FIN; kc += 64) {
        #pragma unroll
        for (int v = 0; v < 2; v++) {
            int idx = tid * 2 + v;
            int row = idx >> 3, seg = idx & 7;
            uint32_t sw = sw128((uint32_t)(row * 128 + seg * 16));
            const size_t off = (size_t)(f0 + row) * FIN + kc + seg * 8;
            CP_ASYNC16(sb + G_AHI + sw, g_WThi + off);
            CP_ASYNC16(sb + G_ALO + sw, g_WTlo + off);
        }
        {
            const size_t off = (size_t)(i0 + tid) * FIN + kc;
            #pragma unroll
            for (int q = 0; q < 8; q++) {
                uint32_t sw = sw128((uint32_t)(tid * 128 + q * 16));
                CP_ASYNC16(sb + G_BHI + sw, g_Xhi + off + q * 8);
                CP_ASYNC16(sb + G_BLO + sw, g_Xlo + off + q * 8);
            }
        }
        CP_COMMIT();
        CP_WAIT0();
        __syncthreads();
        #pragma unroll
        for (int k0 = 0; k0 < 64; k0 += 16) {
            uint32_t Ahi0[4], Alo0[4], Ahi1[4], Alo1[4];
            uint32_t ao0 = sw128((uint32_t)(a_rbase * 128 + (k0 + a_koff) * 2));
            uint32_t ao1 = sw128((uint32_t)((a_rbase + 16) * 128 + (k0 + a_koff) * 2));
            ldsm4(Ahi0, sb + G_AHI + ao0);
            ldsm4(Alo0, sb + G_ALO + ao0);
            ldsm4(Ahi1, sb + G_AHI + ao1);
            ldsm4(Alo1, sb + G_ALO + ao1);
            #pragma unroll
            for (int nb = 0; nb < 4; nb++) {
                uint32_t boff = sw128((uint32_t)((b_roff + nb * 16) * 128 + (k0 + b_koff) * 2));
                uint32_t Bh[4], Bl[4];
                ldsm4(Bh, sb + G_BHI + boff);
                ldsm4(Bl, sb + G_BLO + boff);
                float* d00 = acc + nb * 8;
                float* d01 = acc + nb * 8 + 4;
                float* d10 = acc + 32 + nb * 8;
                float* d11 = acc + 32 + nb * 8 + 4;
                mmaf16(d00, Ahi0, Bh[0], Bh[1]);
                mmaf16(d01, Ahi0, Bh[2], Bh[3]);
                mmaf16(d10, Ahi1, Bh[0], Bh[1]);
                mmaf16(d11, Ahi1, Bh[2], Bh[3]);
                mmaf16(d00, Ahi0, Bl[0], Bl[1]);
                mmaf16(d01, Ahi0, Bl[2], Bl[3]);
                mmaf16(d10, Ahi1, Bl[0], Bl[1]);
                mmaf16(d11, Ahi1, Bl[2], Bl[3]);
                mmaf16(d00, Alo0, Bh[0], Bh[1]);
                mmaf16(d01, Alo0, Bh[2], Bh[3]);
                mmaf16(d10, Alo1, Bh[0], Bh[1]);
                mmaf16(d11, Alo1, Bh[2], Bh[3]);
            }
        }
        __syncthreads();
    }

    {
        const int qr = lane >> 2, qc = lane & 3;
        #pragma unroll
        for (int mt = 0; mt < 2; mt++) {
            int fr = f0 + mw * 32 + mt * 16 + qr;
            #pragma unroll
            for (int nb = 0; nb < 4; nb++) {
                const float* a = acc + mt * 32 + nb * 8;
                int col = i0 + fw * 64 + nb * 16 + 2 * qc;
                __half2 v0 = __floats2half2_rn(a[0], a[1]);
                __half2 v1 = __floats2half2_rn(a[2], a[3]);
                __half2 v2 = __floats2half2_rn(a[4], a[5]);
                __half2 v3 = __floats2half2_rn(a[6], a[7]);
                *(__half2*)(g_hT + (size_t)fr * N + col)           = v0;
                *(__half2*)(g_hT + (size_t)(fr + 8) * N + col)     = v1;
                *(__half2*)(g_hT + (size_t)fr * N + col + 8)       = v2;
                *(__half2*)(g_hT + (size_t)(fr + 8) * N + col + 8) = v3;
            }
        }
    }
}

// ---------------------------------------------------------------------------
// Kernel 4: masked-softmax aggregation via fp16 mma.sync, SINGLE chain.
// R13/R14 proven config (grid 256 static, SPLITS=2, occ 2) with genA
// exponent folded into two per-row constants: e = t>=nu ? t+c1 : 0.2t+c2.
// ---------------------------------------------------------------------------
#define STAGE 40960
#define OFF_A(s) ((s) * STAGE)
#define OFF_B(s) ((s) * STAGE + 8192)
#define SMEM_ATTN (2 * STAGE)   // 81920

__global__ __launch_bounds__(256, 2) void k_attn(const int* __restrict__ adj) {
    extern __shared__ char smem[];
    const uint32_t sb = smem_u32(smem);
    const int tid = threadIdx.x;
    const int bx = blockIdx.x;
    const int i_tile = bx & 127, split = bx >> 7;
    const int i0 = i_tile * ITILE;
    const int jbase = split * JHALF;

    const int warp = tid >> 5, lane = tid & 31;
    const int mw = warp >> 2;
    const int fw = warp & 3;
    const int gr = lane >> 3, lr = lane & 7;
    const int a_rbase = mw * 32 + lr + (gr & 1) * 8;
    const int a_koff = (gr >> 1) * 8;
    const int b_roff = fw * 64 + lr + (gr >> 1) * 8;
    const int b_koff = (gr & 1) * 8;

    const int il = tid >> 2;
    const int jb = (tid & 3) * 16;
    float c1, c2, nu;
    {
        float uu = g_u[i0 + il];
        float T = __int_as_float(g_maxbits) - 64.f;
        float smax = uu + T;
        float b = (smax >= 0.f) ? smax : 0.2f * smax;
        float kk = 13.f - floorf(b);
        nu = -uu;                 // threshold: s >= 0 <=> t >= nu
        c1 = uu + kk;             // e = t + c1        (s >= 0)
        c2 = 0.2f * uu + kk;      // e = 0.2 t + c2    (s < 0)
    }
    const int* adjrow = adj + (size_t)(i0 + il) * N;
    float zacc = 0.f;

    float acc[64];
    #pragma unroll
    for (int q = 0; q < 64; q++) acc[q] = 0.f;

    auto fillB = [&](int s, int jglob) {
        const __half* src = g_hT + (size_t)tid * N + jglob;
        #pragma unroll
        for (int q = 0; q < 8; q++) {
            uint32_t sw = sw128(tid * 128 + q * 16);
            CP_ASYNC16(sb + OFF_B(s) + sw, src + q * 8);
        }
    };
    auto genA = [&](int s, const int4* am4, int jglob) {
        const int* am = (const int*)am4;
        const float4* tp = (const float4*)(g_t + jglob + jb);
        float tv[16];
        #pragma unroll
        for (int q = 0; q < 4; q++) {
            float4 t4 = tp[q];
            tv[q * 4 + 0] = t4.x;
            tv[q * 4 + 1] = t4.y;
            tv[q * 4 + 2] = t4.z;
            tv[q * 4 + 3] = t4.w;
        }
        uint32_t phv[8];
        #pragma unroll
        for (int p = 0; p < 8; p++) {
            float w[2];
            #pragma unroll
            for (int e = 0; e < 2; e++) {
                int jj = p * 2 + e;
                float t = tv[jj];
                float ee = (t >= nu) ? (t + c1) : fmaf(t, 0.2f, c2);
                float wv = ex2(ee);
                w[e] = am[jj] ? wv : 0.f;
            }
            __half2 hh = __floats2half2_rn(w[0], w[1]);
            zacc += __low2float(hh) + __high2float(hh);
            phv[p] = *(uint32_t*)&hh;
        }
        uint32_t sw0 = sw128((uint32_t)(il * 128 + jb * 2));
        uint32_t sw1 = sw128((uint32_t)(il * 128 + jb * 2 + 16));
        *(uint4*)(smem + OFF_A(s) + sw0) = make_uint4(phv[0], phv[1], phv[2], phv[3]);
        *(uint4*)(smem + OFF_A(s) + sw1) = make_uint4(phv[4], phv[5], phv[6], phv[7]);
    };

    {
        int4 aR[4];
        const int4* ap = (const int4*)(adjrow + jbase + jb);
        aR[0] = ap[0]; aR[1] = ap[1]; aR[2] = ap[2]; aR[3] = ap[3];
        fillB(0, jbase);
        CP_COMMIT();
        genA(0, aR, jbase);
        CP_WAIT0();
        __syncthreads();
    }

    for (int c = 0; c < NCHUNK; c++) {
        const int s = c & 1;
        const bool more = (c + 1 < NCHUNK);
        int4 aR[4];
        int jn = jbase + (c + 1) * JT;
        if (more) {
            const int4* ap = (const int4*)(adjrow + jn + jb);
            aR[0] = ap[0]; aR[1] = ap[1]; aR[2] = ap[2]; aR[3] = ap[3];
            fillB(s ^ 1, jn);
            CP_COMMIT();
        }
        #pragma unroll
        for (int k0 = 0; k0 < JT; k0 += 16) {
            uint32_t A0[4], A1[4], B[4][4];
            uint32_t ao0 = sw128((uint32_t)(a_rbase * 128 + (k0 + a_koff) * 2));
            uint32_t ao1 = sw128((uint32_t)((a_rbase + 16) * 128 + (k0 + a_koff) * 2));
            ldsm4(A0, sb + OFF_A(s) + ao0);
            ldsm4(A1, sb + OFF_A(s) + ao1);
            #pragma unroll
            for (int nb = 0; nb < 4; nb++) {
                uint32_t boff = sw128((uint32_t)((b_roff + nb * 16) * 128 + (k0 + b_koff) * 2));
                ldsm4(B[nb], sb + OFF_B(s) + boff);
            }
            #pragma unroll
            for (int nb = 0; nb < 4; nb++) {
                mmaf16(acc + nb * 8,          A0, B[nb][0], B[nb][1]);
                mmaf16(acc + nb * 8 + 4,      A0, B[nb][2], B[nb][3]);
                mmaf16(acc + 32 + nb * 8,     A1, B[nb][0], B[nb][1]);
                mmaf16(acc + 32 + nb * 8 + 4, A1, B[nb][2], B[nb][3]);
            }
        }
        if (more) {
            genA(s ^ 1, aR, jn);
            CP_WAIT0();
        }
        __syncthreads();
    }

    zacc += __shfl_xor_sync(0xFFFFFFFFu, zacc, 1);
    zacc += __shfl_xor_sync(0xFFFFFFFFu, zacc, 2);
    if ((tid & 3) == 0) g_pz[bx * ITILE + il] = zacc;

    {
        const int qr = lane >> 2, qc = lane & 3;
        #pragma unroll
        for (int mt = 0; mt < 2; mt++) {
            int r0 = mw * 32 + mt * 16 + qr;
            float* base0 = g_pnum + (size_t)bx * (ITILE * 256)
                         + (size_t)r0 * 256 + fw * 64 + 2 * qc;
            float* base1 = base0 + 8 * 256;
            #pragma unroll
            for (int nb = 0; nb < 4; nb++) {
                const float* a = acc + mt * 32 + nb * 8;
                *(float2*)(base0 + nb * 16)     = make_float2(a[0], a[1]);
                *(float2*)(base1 + nb * 16)     = make_float2(a[2], a[3]);
                *(float2*)(base0 + nb * 16 + 8) = make_float2(a[4], a[5]);
                *(float2*)(base1 + nb * 16 + 8) = make_float2(a[6], a[7]);
            }
        }
    }
}

// ---------------------------------------------------------------------------
// Kernel 5: combine splits, normalize, ELU
// ---------------------------------------------------------------------------
__global__ __launch_bounds__(256) void k_comb(float* __restrict__ out) {
    int gid = blockIdx.x * 256 + threadIdx.x;
    int i = gid >> 6;
    int c4 = (gid & 63) * 4;
    int it = i >> 6, row = i & 63;
    size_t b0 = (size_t)it * (ITILE * 256) + (size_t)row * 256 + c4;
    float4 n0 = *(const float4*)(g_pnum + b0);
    float4 n1 = *(const float4*)(g_pnum + b0 + (size_t)128 * (ITILE * 256));
    float z = g_pz[it * ITILE + row] + g_pz[(128 + it) * ITILE + row];
    float inv = 1.f / z;
    float v0 = (n0.x + n1.x) * inv;
    float v1 = (n0.y + n1.y) * inv;
    float v2 = (n0.z + n1.z) * inv;
    float v3 = (n0.w + n1.w) * inv;
    float4 o;
    o.x = (v0 > 0.f) ? v0 : expm1f(v0);
    o.y = (v1 > 0.f) ? v1 : expm1f(v1);
    o.z = (v2 > 0.f) ? v2 : expm1f(v2);
    o.w = (v3 > 0.f) ? v3 : expm1f(v3);
    *(float4*)(out + (size_t)i * FOUT + c4) = o;
}

// ---------------------------------------------------------------------------
extern "C" void kernel_launch(void* const* d_in, const int* in_sizes, int n_in,
                              void* d_out, int out_size) {
    (void)in_sizes; (void)n_in; (void)out_size;
    const float* X   = (const float*)d_in[0];
    const int*   adj = (const int*)d_in[1];
    const float* W   = (const float*)d_in[2];
    const float* a1  = (const float*)d_in[3];
    const float* a2  = (const float*)d_in[4];
    float* out = (float*)d_out;

    cudaFuncSetAttribute(k_attn, cudaFuncAttributeMaxDynamicSharedMemorySize, SMEM_ATTN);
    cudaFuncSetAttribute(k_gemm2, cudaFuncAttributeMaxDynamicSharedMemorySize, SMEM_GEMM);

    k_wa<<<FIN / 8, 256>>>(W, a1, a2);
    k_f<<<N / 8, 256>>>(X);
    k_wt<<<dim3(FIN / 32, FOUT / 32), dim3(32, 8)>>>(W);
    k_gemm2<<<dim3(FOUT / 64, N / 256), 256, SMEM_GEMM>>>();
    k_attn<<<256, 256, SMEM_ATTN>>>(adj);
    k_comb<<<(N * FOUT / 4) / 256, 256>>>(out);
}